// round 3
// baseline (speedup 1.0000x reference)
#include <cuda_runtime.h>
#include <math.h>
#include <stdint.h>

// ---------------- problem constants ----------------
#define BATCH   2
#define HT      64
#define WT      64
#define CDIM    768
#define WIN     14
#define NWIN1   5              // ceil(64/14)
#define NWINB   25             // 5*5 windows per batch image
#define NW      50             // total windows
#define HW      196            // tokens per window
#define NHEAD   12
#define HD      64
#define MLPD    3072
#define TOKW    (NW*HW)        // 9800 windowed tokens
#define TOKG    (BATCH*HT*WT)  // 8192 global tokens
#define EPS     1e-5f

// ---------------- scratch (device globals; no allocs allowed) ----------------
__device__ float g_xw  [TOKW * CDIM];      // LN1 output, windowed layout (zero padded)
__device__ float g_qkv [TOKW * 3 * CDIM];  // qkv
__device__ float g_attn[TOKW * CDIM];      // attention output
__device__ float g_x2  [TOKG * CDIM];      // x + attn (after unpartition)
__device__ float g_xn2 [TOKG * CDIM];      // LN2 output
__device__ float g_hid [TOKG * MLPD];      // MLP hidden

// ---------------- helpers ----------------
__device__ __forceinline__ void win_map(int row, int& gidx, bool& valid) {
    int n  = row / HW, t = row % HW;
    int bb = n / NWINB, nw = n % NWINB;
    int wh = nw / NWIN1, ww = nw % NWIN1;
    int ii = t / WIN,    jj = t % WIN;
    int gh = wh * WIN + ii, gw = ww * WIN + jj;
    valid = (gh < HT) && (gw < WT);
    gidx  = (bb * HT + gh) * WT + gw;
}

__device__ __forceinline__ float to_tf32(float x) {
    uint32_t u;
    asm("cvt.rna.tf32.f32 %0, %1;" : "=r"(u) : "f"(x));
    return __uint_as_float(u);
}

// ---------------- LayerNorm kernels ----------------
__global__ __launch_bounds__(256) void ln_win_kernel(
    const float* __restrict__ x, const float* __restrict__ g,
    const float* __restrict__ b)
{
    int row = blockIdx.x;
    int tid = threadIdx.x;
    float* orow = g_xw + (size_t)row * CDIM;

    int gidx; bool valid;
    win_map(row, gidx, valid);
    if (!valid) {
        for (int c = tid; c < CDIM; c += 256) orow[c] = 0.f;
        return;
    }
    const float* xr = x + (size_t)gidx * CDIM;
    float v[3]; float s = 0.f, sq = 0.f;
    #pragma unroll
    for (int u = 0; u < 3; u++) {
        v[u] = xr[tid + u * 256];
        s += v[u]; sq += v[u] * v[u];
    }
    __shared__ float red[2][8];
    #pragma unroll
    for (int off = 16; off; off >>= 1) {
        s  += __shfl_xor_sync(~0u, s,  off);
        sq += __shfl_xor_sync(~0u, sq, off);
    }
    if ((tid & 31) == 0) { red[0][tid >> 5] = s; red[1][tid >> 5] = sq; }
    __syncthreads();
    if (tid < 32) {
        float a = (tid < 8) ? red[0][tid] : 0.f;
        float c = (tid < 8) ? red[1][tid] : 0.f;
        #pragma unroll
        for (int off = 4; off; off >>= 1) {
            a += __shfl_xor_sync(~0u, a, off);
            c += __shfl_xor_sync(~0u, c, off);
        }
        if (tid == 0) { red[0][0] = a; red[1][0] = c; }
    }
    __syncthreads();
    float mean = red[0][0] * (1.f / CDIM);
    float var  = red[1][0] * (1.f / CDIM) - mean * mean;
    float rstd = rsqrtf(var + EPS);
    #pragma unroll
    for (int u = 0; u < 3; u++) {
        int c = tid + u * 256;
        orow[c] = (v[u] - mean) * rstd * g[c] + b[c];
    }
}

__global__ __launch_bounds__(256) void ln2_kernel(
    const float* __restrict__ g, const float* __restrict__ b)
{
    int row = blockIdx.x;
    int tid = threadIdx.x;
    const float* xr = g_x2 + (size_t)row * CDIM;
    float* orow = g_xn2 + (size_t)row * CDIM;
    float v[3]; float s = 0.f, sq = 0.f;
    #pragma unroll
    for (int u = 0; u < 3; u++) {
        v[u] = xr[tid + u * 256];
        s += v[u]; sq += v[u] * v[u];
    }
    __shared__ float red[2][8];
    #pragma unroll
    for (int off = 16; off; off >>= 1) {
        s  += __shfl_xor_sync(~0u, s,  off);
        sq += __shfl_xor_sync(~0u, sq, off);
    }
    if ((tid & 31) == 0) { red[0][tid >> 5] = s; red[1][tid >> 5] = sq; }
    __syncthreads();
    if (tid < 32) {
        float a = (tid < 8) ? red[0][tid] : 0.f;
        float c = (tid < 8) ? red[1][tid] : 0.f;
        #pragma unroll
        for (int off = 4; off; off >>= 1) {
            a += __shfl_xor_sync(~0u, a, off);
            c += __shfl_xor_sync(~0u, c, off);
        }
        if (tid == 0) { red[0][0] = a; red[1][0] = c; }
    }
    __syncthreads();
    float mean = red[0][0] * (1.f / CDIM);
    float var  = red[1][0] * (1.f / CDIM) - mean * mean;
    float rstd = rsqrtf(var + EPS);
    #pragma unroll
    for (int u = 0; u < 3; u++) {
        int c = tid + u * 256;
        orow[c] = (v[u] - mean) * rstd * g[c] + b[c];
    }
}

// ---------------- TF32 tensor-core GEMM with fused epilogues ----------------
// C[M,N] = A[M,K] @ B[K,N] + bias
// mode 0: plain store            (QKV)
// mode 1: exact GELU             (FC1)
// mode 2: += res[row]            (FC2 -> d_out)
// mode 3: window-unpartition: out[gidx] = xin[gidx] + acc  (proj)
//
// 128x128x16 block tile, 256 threads = 8 warps (2x4), warp tile 64x32,
// mma.sync.m16n8k8.tf32 with fp32 accumulate.
#define ASTRIDE 20
#define BSTRIDE 136

__global__ __launch_bounds__(256, 2) void tgemm_kernel(
    const float* __restrict__ A, const float* __restrict__ Bm,
    const float* __restrict__ bias, const float* __restrict__ res,
    const float* __restrict__ xin, float* __restrict__ Cc,
    int M, int N, int K, int mode)
{
    __shared__ float As[128][ASTRIDE];   // [m][k], conflict-free frag loads
    __shared__ float Bs[16][BSTRIDE];    // [k][n]

    int tid  = threadIdx.x;
    int warp = tid >> 5, lane = tid & 31;
    int wm = warp >> 2, wn = warp & 3;   // 2 x 4 warps
    int gq = lane >> 2, tr = lane & 3;   // groupID, threadInGroup
    int bm = blockIdx.y * 128, bn = blockIdx.x * 128;

    // A loads: thread -> row tid>>1, cols (tid&1)*8 .. +7
    int arow = tid >> 1;
    int acol = (tid & 1) * 8;
    bool avalid = (bm + arow) < M;
    const float* Aptr = A + (size_t)(bm + arow) * K + acol;
    // B loads: thread -> row tid>>4, cols (tid&15)*8 .. +7
    int brow = tid >> 4;
    int bcol = (tid & 15) * 8;
    const float* Bptr = Bm + (size_t)brow * N + bn + bcol;

    float acc[4][4][4];
    #pragma unroll
    for (int mi = 0; mi < 4; mi++)
        #pragma unroll
        for (int ni = 0; ni < 4; ni++)
            #pragma unroll
            for (int r = 0; r < 4; r++) acc[mi][ni][r] = 0.f;

    for (int k0 = 0; k0 < K; k0 += 16) {
        float4 a0 = make_float4(0.f, 0.f, 0.f, 0.f), a1 = a0;
        if (avalid) {
            a0 = *(const float4*)(Aptr + k0);
            a1 = *(const float4*)(Aptr + k0 + 4);
        }
        const float* bp = Bptr + (size_t)k0 * N;
        float4 b0 = *(const float4*)(bp);
        float4 b1 = *(const float4*)(bp + 4);

        float4 t;
        t.x = to_tf32(a0.x); t.y = to_tf32(a0.y);
        t.z = to_tf32(a0.z); t.w = to_tf32(a0.w);
        *(float4*)&As[arow][acol] = t;
        t.x = to_tf32(a1.x); t.y = to_tf32(a1.y);
        t.z = to_tf32(a1.z); t.w = to_tf32(a1.w);
        *(float4*)&As[arow][acol + 4] = t;
        t.x = to_tf32(b0.x); t.y = to_tf32(b0.y);
        t.z = to_tf32(b0.z); t.w = to_tf32(b0.w);
        *(float4*)&Bs[brow][bcol] = t;
        t.x = to_tf32(b1.x); t.y = to_tf32(b1.y);
        t.z = to_tf32(b1.z); t.w = to_tf32(b1.w);
        *(float4*)&Bs[brow][bcol + 4] = t;
        __syncthreads();

        #pragma unroll
        for (int kk = 0; kk < 16; kk += 8) {
            uint32_t af[4][4], bf[4][2];
            #pragma unroll
            for (int mi = 0; mi < 4; mi++) {
                int m0 = wm * 64 + mi * 16;
                af[mi][0] = __float_as_uint(As[m0 + gq    ][kk + tr]);
                af[mi][1] = __float_as_uint(As[m0 + gq + 8][kk + tr]);
                af[mi][2] = __float_as_uint(As[m0 + gq    ][kk + tr + 4]);
                af[mi][3] = __float_as_uint(As[m0 + gq + 8][kk + tr + 4]);
            }
            #pragma unroll
            for (int ni = 0; ni < 4; ni++) {
                int n0 = wn * 32 + ni * 8;
                bf[ni][0] = __float_as_uint(Bs[kk + tr    ][n0 + gq]);
                bf[ni][1] = __float_as_uint(Bs[kk + tr + 4][n0 + gq]);
            }
            #pragma unroll
            for (int mi = 0; mi < 4; mi++)
                #pragma unroll
                for (int ni = 0; ni < 4; ni++) {
                    asm volatile(
                        "mma.sync.aligned.m16n8k8.row.col.f32.tf32.tf32.f32 "
                        "{%0,%1,%2,%3}, {%4,%5,%6,%7}, {%8,%9}, {%0,%1,%2,%3};\n"
                        : "+f"(acc[mi][ni][0]), "+f"(acc[mi][ni][1]),
                          "+f"(acc[mi][ni][2]), "+f"(acc[mi][ni][3])
                        : "r"(af[mi][0]), "r"(af[mi][1]),
                          "r"(af[mi][2]), "r"(af[mi][3]),
                          "r"(bf[ni][0]), "r"(bf[ni][1]));
                }
        }
        __syncthreads();
    }

    // ---------------- epilogue ----------------
    #pragma unroll
    for (int mi = 0; mi < 4; mi++) {
        int rbase = bm + wm * 64 + mi * 16 + gq;
        #pragma unroll
        for (int h = 0; h < 2; h++) {
            int row = rbase + 8 * h;
            if (row >= M) continue;
            int gidx = 0; bool valid = true;
            if (mode == 3) {
                win_map(row, gidx, valid);
                if (!valid) continue;
            }
            #pragma unroll
            for (int ni = 0; ni < 4; ni++) {
                int col = bn + wn * 32 + ni * 8 + tr * 2;
                float v0 = acc[mi][ni][2 * h]     + bias[col];
                float v1 = acc[mi][ni][2 * h + 1] + bias[col + 1];
                if (mode == 1) {
                    v0 = 0.5f * v0 * (1.f + erff(v0 * 0.70710678118654752f));
                    v1 = 0.5f * v1 * (1.f + erff(v1 * 0.70710678118654752f));
                    Cc[(size_t)row * N + col]     = v0;
                    Cc[(size_t)row * N + col + 1] = v1;
                } else if (mode == 2) {
                    Cc[(size_t)row * N + col]     = v0 + res[(size_t)row * N + col];
                    Cc[(size_t)row * N + col + 1] = v1 + res[(size_t)row * N + col + 1];
                } else if (mode == 3) {
                    Cc[(size_t)gidx * N + col]     = v0 + xin[(size_t)gidx * N + col];
                    Cc[(size_t)gidx * N + col + 1] = v1 + xin[(size_t)gidx * N + col + 1];
                } else {
                    Cc[(size_t)row * N + col]     = v0;
                    Cc[(size_t)row * N + col + 1] = v1;
                }
            }
        }
    }
}

// ---------------- fused window attention ----------------
#define KV_STRIDE 65
#define ATTN_SMEM_FLOATS (HW*KV_STRIDE*2 + 27*HD*2 + 8*HD + 8*28 + 8*HW)

__global__ __launch_bounds__(256) void attn_kernel(
    const float* __restrict__ rel_h, const float* __restrict__ rel_w)
{
    extern __shared__ float sm[];
    float* ks = sm;                       // [196][65]
    float* vs = ks + HW * KV_STRIDE;      // [196][65]
    float* rh = vs + HW * KV_STRIDE;      // [27][64]
    float* rw = rh + 27 * HD;             // [27][64]
    float* qs = rw + 27 * HD;             // [8][64]
    float* bs = qs + 8 * HD;              // [8][28]
    float* ps = bs + 8 * 28;              // [8][196]

    int w0   = blockIdx.x;
    int head = blockIdx.y;
    int tid  = threadIdx.x;
    int warp = tid >> 5, lane = tid & 31;

    const float* qkv_base = g_qkv + (size_t)w0 * HW * (3 * CDIM) + head * HD;
    for (int idx = tid; idx < HW * HD; idx += 256) {
        int kt = idx / HD, d = idx % HD;
        const float* src = qkv_base + (size_t)kt * (3 * CDIM);
        ks[kt * KV_STRIDE + d] = src[CDIM + d];
        vs[kt * KV_STRIDE + d] = src[2 * CDIM + d];
    }
    for (int idx = tid; idx < 27 * HD; idx += 256) rh[idx] = rel_h[idx];
    for (int idx = tid; idx < 27 * HD; idx += 256) rw[idx] = rel_w[idx];
    __syncthreads();

    for (int r = warp; r < HW; r += 8) {
        size_t row = (size_t)w0 * HW + r;
        const float* qp = g_qkv + row * (3 * CDIM) + head * HD;
        qs[warp * HD + lane]      = qp[lane];
        qs[warp * HD + lane + 32] = qp[lane + 32];
        __syncwarp();

        int hq = r / WIN, wq = r % WIN;
        if (lane < 28) {
            const float* tab; int o;
            if (lane < 14) { tab = rh; o = (hq - lane + (WIN - 1)) * HD; }
            else           { tab = rw; o = (wq - (lane - 14) + (WIN - 1)) * HD; }
            float sacc = 0.f;
            #pragma unroll 16
            for (int d = 0; d < HD; d++) sacc += qs[warp * HD + d] * tab[o + d];
            bs[warp * 28 + lane] = sacc;
        }
        __syncwarp();

        float sc[7];
        float mx = -1e30f;
        #pragma unroll
        for (int s = 0; s < 7; s++) {
            int key = lane + 32 * s;
            if (key < HW) {
                float acc = 0.f;
                #pragma unroll 16
                for (int d = 0; d < HD; d++)
                    acc += qs[warp * HD + d] * ks[key * KV_STRIDE + d];
                acc = acc * 0.125f
                    + bs[warp * 28 + key / WIN]
                    + bs[warp * 28 + 14 + key % WIN];
                sc[s] = acc;
                mx = fmaxf(mx, acc);
            } else sc[s] = -1e30f;
        }
        #pragma unroll
        for (int off = 16; off; off >>= 1)
            mx = fmaxf(mx, __shfl_xor_sync(~0u, mx, off));
        float sum = 0.f;
        #pragma unroll
        for (int s = 0; s < 7; s++) {
            int key = lane + 32 * s;
            if (key < HW) { float e = __expf(sc[s] - mx); sc[s] = e; sum += e; }
            else sc[s] = 0.f;
        }
        #pragma unroll
        for (int off = 16; off; off >>= 1)
            sum += __shfl_xor_sync(~0u, sum, off);
        float inv = 1.f / sum;
        #pragma unroll
        for (int s = 0; s < 7; s++) {
            int key = lane + 32 * s;
            if (key < HW) ps[warp * HW + key] = sc[s] * inv;
        }
        __syncwarp();

        float o0 = 0.f, o1 = 0.f;
        for (int k2 = 0; k2 < HW; k2++) {
            float p = ps[warp * HW + k2];
            o0 = fmaf(p, vs[k2 * KV_STRIDE + lane],      o0);
            o1 = fmaf(p, vs[k2 * KV_STRIDE + lane + 32], o1);
        }
        float* op = g_attn + row * CDIM + head * HD;
        op[lane]      = o0;
        op[lane + 32] = o1;
        __syncwarp();
    }
}

// ---------------- launcher ----------------
extern "C" void kernel_launch(void* const* d_in, const int* in_sizes, int n_in,
                              void* d_out, int out_size)
{
    const float* x      = (const float*)d_in[0];
    const float* g1     = (const float*)d_in[1];
    const float* b1     = (const float*)d_in[2];
    const float* w_qkv  = (const float*)d_in[3];
    const float* b_qkv  = (const float*)d_in[4];
    const float* w_proj = (const float*)d_in[5];
    const float* b_proj = (const float*)d_in[6];
    const float* rel_h  = (const float*)d_in[7];
    const float* rel_w  = (const float*)d_in[8];
    const float* g2     = (const float*)d_in[9];
    const float* b2     = (const float*)d_in[10];
    const float* w1     = (const float*)d_in[11];
    const float* b1m    = (const float*)d_in[12];
    const float* w2     = (const float*)d_in[13];
    const float* b2m    = (const float*)d_in[14];
    float* out = (float*)d_out;

    float *p_xw, *p_qkv, *p_attn, *p_x2, *p_xn2, *p_hid;
    cudaGetSymbolAddress((void**)&p_xw,   g_xw);
    cudaGetSymbolAddress((void**)&p_qkv,  g_qkv);
    cudaGetSymbolAddress((void**)&p_attn, g_attn);
    cudaGetSymbolAddress((void**)&p_x2,   g_x2);
    cudaGetSymbolAddress((void**)&p_xn2,  g_xn2);
    cudaGetSymbolAddress((void**)&p_hid,  g_hid);

    static int attr_set = 0;
    if (!attr_set) {
        cudaFuncSetAttribute(attn_kernel,
            cudaFuncAttributeMaxDynamicSharedMemorySize,
            ATTN_SMEM_FLOATS * sizeof(float));
        attr_set = 1;
    }

    // 1) LN1 + window partition -> g_xw [9800, 768]
    ln_win_kernel<<<TOKW, 256>>>(x, g1, b1);

    // 2) QKV GEMM: [9800,768] @ [768,2304]
    {
        dim3 grid((3 * CDIM) / 128, (TOKW + 127) / 128);
        tgemm_kernel<<<grid, 256>>>(p_xw, w_qkv, b_qkv, nullptr, nullptr,
                                    p_qkv, TOKW, 3 * CDIM, CDIM, 0);
    }

    // 3) fused attention per (window, head)
    attn_kernel<<<dim3(NW, NHEAD), 256, ATTN_SMEM_FLOATS * sizeof(float)>>>(rel_h, rel_w);

    // 4) proj GEMM + window unpartition + residual -> g_x2 [8192, 768]
    {
        dim3 grid(CDIM / 128, (TOKW + 127) / 128);
        tgemm_kernel<<<grid, 256>>>(p_attn, w_proj, b_proj, nullptr, x,
                                    p_x2, TOKW, CDIM, CDIM, 3);
    }

    // 5) LN2 -> g_xn2
    ln2_kernel<<<TOKG, 256>>>(g2, b2);

    // 6) FC1 + GELU: [8192,768] @ [768,3072]
    {
        dim3 grid(MLPD / 128, TOKG / 128);
        tgemm_kernel<<<grid, 256>>>(p_xn2, w1, b1m, nullptr, nullptr,
                                    p_hid, TOKG, MLPD, CDIM, 1);
    }

    // 7) FC2 + residual: [8192,3072] @ [3072,768] -> out
    {
        dim3 grid(CDIM / 128, TOKG / 128);
        tgemm_kernel<<<grid, 256>>>(p_hid, w2, b2m, p_x2, nullptr,
                                    out, TOKG, CDIM, MLPD, 2);
    }
}

// round 4
// speedup vs baseline: 1.5031x; 1.5031x over previous
#include <cuda_runtime.h>
#include <math.h>
#include <stdint.h>

// ---------------- problem constants ----------------
#define BATCH   2
#define HT      64
#define WT      64
#define CDIM    768
#define WIN     14
#define NWIN1   5
#define NWINB   25
#define NW      50
#define HW      196
#define NHEAD   12
#define HD      64
#define MLPD    3072
#define TOKW    (NW*HW)        // 9800
#define TOKG    (BATCH*HT*WT)  // 8192
#define EPS     1e-5f

// ---------------- scratch ----------------
__device__ float g_xw  [TOKW * CDIM];
__device__ float g_qkv [TOKW * 3 * CDIM];
__device__ float g_attn[TOKW * CDIM];
__device__ float g_x2  [TOKG * CDIM];
__device__ float g_xn2 [TOKG * CDIM];
__device__ float g_hid [TOKG * MLPD];

// ---------------- helpers ----------------
__device__ __forceinline__ void win_map(int row, int& gidx, bool& valid) {
    int n  = row / HW, t = row % HW;
    int bb = n / NWINB, nw = n % NWINB;
    int wh = nw / NWIN1, ww = nw % NWIN1;
    int ii = t / WIN,    jj = t % WIN;
    int gh = wh * WIN + ii, gw = ww * WIN + jj;
    valid = (gh < HT) && (gw < WT);
    gidx  = (bb * HT + gh) * WT + gw;
}

__device__ __forceinline__ uint32_t smem_u32(const void* p) {
    return (uint32_t)__cvta_generic_to_shared(p);
}
__device__ __forceinline__ void cp16(uint32_t dst, const void* src, bool v) {
    int sz = v ? 16 : 0;
    asm volatile("cp.async.cg.shared.global [%0], [%1], 16, %2;\n"
                 :: "r"(dst), "l"(src), "r"(sz));
}
__device__ __forceinline__ void ldsm4(uint32_t& r0, uint32_t& r1,
                                      uint32_t& r2, uint32_t& r3, uint32_t a) {
    asm volatile("ldmatrix.sync.aligned.m8n8.x4.shared.b16 {%0,%1,%2,%3}, [%4];"
                 : "=r"(r0), "=r"(r1), "=r"(r2), "=r"(r3) : "r"(a));
}

// ---------------- LayerNorm kernels ----------------
__global__ __launch_bounds__(256) void ln_win_kernel(
    const float* __restrict__ x, const float* __restrict__ g,
    const float* __restrict__ b)
{
    int row = blockIdx.x;
    int tid = threadIdx.x;
    float* orow = g_xw + (size_t)row * CDIM;

    int gidx; bool valid;
    win_map(row, gidx, valid);
    if (!valid) {
        for (int c = tid; c < CDIM; c += 256) orow[c] = 0.f;
        return;
    }
    const float* xr = x + (size_t)gidx * CDIM;
    float v[3]; float s = 0.f, sq = 0.f;
    #pragma unroll
    for (int u = 0; u < 3; u++) {
        v[u] = xr[tid + u * 256];
        s += v[u]; sq += v[u] * v[u];
    }
    __shared__ float red[2][8];
    #pragma unroll
    for (int off = 16; off; off >>= 1) {
        s  += __shfl_xor_sync(~0u, s,  off);
        sq += __shfl_xor_sync(~0u, sq, off);
    }
    if ((tid & 31) == 0) { red[0][tid >> 5] = s; red[1][tid >> 5] = sq; }
    __syncthreads();
    if (tid < 32) {
        float a = (tid < 8) ? red[0][tid] : 0.f;
        float c = (tid < 8) ? red[1][tid] : 0.f;
        #pragma unroll
        for (int off = 4; off; off >>= 1) {
            a += __shfl_xor_sync(~0u, a, off);
            c += __shfl_xor_sync(~0u, c, off);
        }
        if (tid == 0) { red[0][0] = a; red[1][0] = c; }
    }
    __syncthreads();
    float mean = red[0][0] * (1.f / CDIM);
    float var  = red[1][0] * (1.f / CDIM) - mean * mean;
    float rstd = rsqrtf(var + EPS);
    #pragma unroll
    for (int u = 0; u < 3; u++) {
        int c = tid + u * 256;
        orow[c] = (v[u] - mean) * rstd * g[c] + b[c];
    }
}

__global__ __launch_bounds__(256) void ln2_kernel(
    const float* __restrict__ g, const float* __restrict__ b)
{
    int row = blockIdx.x;
    int tid = threadIdx.x;
    const float* xr = g_x2 + (size_t)row * CDIM;
    float* orow = g_xn2 + (size_t)row * CDIM;
    float v[3]; float s = 0.f, sq = 0.f;
    #pragma unroll
    for (int u = 0; u < 3; u++) {
        v[u] = xr[tid + u * 256];
        s += v[u]; sq += v[u] * v[u];
    }
    __shared__ float red[2][8];
    #pragma unroll
    for (int off = 16; off; off >>= 1) {
        s  += __shfl_xor_sync(~0u, s,  off);
        sq += __shfl_xor_sync(~0u, sq, off);
    }
    if ((tid & 31) == 0) { red[0][tid >> 5] = s; red[1][tid >> 5] = sq; }
    __syncthreads();
    if (tid < 32) {
        float a = (tid < 8) ? red[0][tid] : 0.f;
        float c = (tid < 8) ? red[1][tid] : 0.f;
        #pragma unroll
        for (int off = 4; off; off >>= 1) {
            a += __shfl_xor_sync(~0u, a, off);
            c += __shfl_xor_sync(~0u, c, off);
        }
        if (tid == 0) { red[0][0] = a; red[1][0] = c; }
    }
    __syncthreads();
    float mean = red[0][0] * (1.f / CDIM);
    float var  = red[1][0] * (1.f / CDIM) - mean * mean;
    float rstd = rsqrtf(var + EPS);
    #pragma unroll
    for (int u = 0; u < 3; u++) {
        int c = tid + u * 256;
        orow[c] = (v[u] - mean) * rstd * g[c] + b[c];
    }
}

// ---------------- TF32 tensor-core GEMM, ldmatrix + cp.async pipeline -------
// C[M,N] = A[M,K] @ B[K,N] + bias
// mode 0: plain   1: exact GELU   2: += res[row]   3: window-unpartition + xin
#define ASTRIDE 20
#define ABUFB   (128 * ASTRIDE * 4)   // bytes per buffer

__global__ __launch_bounds__(256, 2) void tgemm_kernel(
    const float* __restrict__ A, const float* __restrict__ Bm,
    const float* __restrict__ bias, const float* __restrict__ res,
    const float* __restrict__ xin, float* __restrict__ Cc,
    int M, int N, int K, int mode)
{
    __shared__ float As[2][128][ASTRIDE];   // [m][k]
    __shared__ float Bt[2][128][ASTRIDE];   // [n][k]  (transposed)

    int tid  = threadIdx.x;
    int warp = tid >> 5, lane = tid & 31;
    int wm = warp >> 2, wn = warp & 3;      // 2 x 4 warps, warp tile 64x32
    int gq = lane >> 2, tr = lane & 3;
    int bm = blockIdx.y * 128, bn = blockIdx.x * 128;

    // ---- A staging (cp.async): row tid>>1, 2 x 16B at cols (tid&1)*8, +4
    int arow = tid >> 1;
    int acol = (tid & 1) * 8;
    int arow_g = bm + arow;
    bool aval = arow_g < M;
    if (arow_g >= M) arow_g = M - 1;
    const float* Ag = A + (size_t)arow_g * K + acol;
    uint32_t as_st = smem_u32(&As[0][arow][acol]);

    // ---- B staging: thread covers n = tid&127, k rows blk..blk+7
    int bln = tid & 127;
    int blk = (tid >> 7) * 8;
    const float* Bg = Bm + (size_t)blk * N + bn + bln;
    float* bt_st = &Bt[0][bln][blk];

    // ---- ldmatrix lane offsets
    uint32_t as_base = smem_u32(&As[0][0][0]);
    uint32_t bt_base = smem_u32(&Bt[0][0][0]);
    int a_r = lane & 15;
    int a_c = (lane >> 4) << 2;
    int b_r = ((lane >> 4) << 3) + (lane & 7);
    int b_c = ((lane >> 3) & 1) << 2;

    float acc[4][4][4];
    #pragma unroll
    for (int mi = 0; mi < 4; mi++)
        #pragma unroll
        for (int ni = 0; ni < 4; ni++)
            #pragma unroll
            for (int r = 0; r < 4; r++) acc[mi][ni][r] = 0.f;

    int T = K / 16;
    float bregs[8];

    // prologue: B tile 0 -> regs, A tile 0 -> smem
    #pragma unroll
    for (int i = 0; i < 8; i++) bregs[i] = Bg[(size_t)i * N];
    cp16(as_st,      Ag,     aval);
    cp16(as_st + 16, Ag + 4, aval);
    asm volatile("cp.async.commit_group;\n");

    for (int t = 0; t < T; t++) {
        int cur = t & 1, nxt = cur ^ 1;
        bool more = (t + 1) < T;
        if (more) {
            const float* ag = Ag + (t + 1) * 16;
            cp16(as_st + nxt * ABUFB,      ag,     aval);
            cp16(as_st + nxt * ABUFB + 16, ag + 4, aval);
            asm volatile("cp.async.commit_group;\n");
            asm volatile("cp.async.wait_group 1;\n");
        } else {
            asm volatile("cp.async.wait_group 0;\n");
        }
        // store B regs into Bt[cur] (conflict-free STS.128)
        float* bd = bt_st + cur * (128 * ASTRIDE);
        *(float4*)bd       = make_float4(bregs[0], bregs[1], bregs[2], bregs[3]);
        *(float4*)(bd + 4) = make_float4(bregs[4], bregs[5], bregs[6], bregs[7]);
        __syncthreads();

        if (more) {
            const float* bg = Bg + (size_t)(t + 1) * 16 * N;
            #pragma unroll
            for (int i = 0; i < 8; i++) bregs[i] = bg[(size_t)i * N];
        }

        // ---- compute on buffers [cur]
        uint32_t ab = as_base + cur * ABUFB;
        uint32_t bb = bt_base + cur * ABUFB;
        #pragma unroll
        for (int kk = 0; kk < 16; kk += 8) {
            uint32_t af[4][4], bf[4][2];
            #pragma unroll
            for (int mi = 0; mi < 4; mi++) {
                uint32_t addr = ab +
                    (((wm * 64 + mi * 16 + a_r) * ASTRIDE) + kk + a_c) * 4;
                ldsm4(af[mi][0], af[mi][1], af[mi][2], af[mi][3], addr);
            }
            #pragma unroll
            for (int nh = 0; nh < 2; nh++) {
                uint32_t addr = bb +
                    (((wn * 32 + nh * 16 + b_r) * ASTRIDE) + kk + b_c) * 4;
                ldsm4(bf[2 * nh][0], bf[2 * nh][1],
                      bf[2 * nh + 1][0], bf[2 * nh + 1][1], addr);
            }
            #pragma unroll
            for (int mi = 0; mi < 4; mi++)
                #pragma unroll
                for (int ni = 0; ni < 4; ni++) {
                    asm volatile(
                        "mma.sync.aligned.m16n8k8.row.col.f32.tf32.tf32.f32 "
                        "{%0,%1,%2,%3}, {%4,%5,%6,%7}, {%8,%9}, {%0,%1,%2,%3};\n"
                        : "+f"(acc[mi][ni][0]), "+f"(acc[mi][ni][1]),
                          "+f"(acc[mi][ni][2]), "+f"(acc[mi][ni][3])
                        : "r"(af[mi][0]), "r"(af[mi][1]),
                          "r"(af[mi][2]), "r"(af[mi][3]),
                          "r"(bf[ni][0]), "r"(bf[ni][1]));
                }
        }
        __syncthreads();
    }

    // ---------------- epilogue ----------------
    #pragma unroll
    for (int mi = 0; mi < 4; mi++) {
        int rbase = bm + wm * 64 + mi * 16 + gq;
        #pragma unroll
        for (int h = 0; h < 2; h++) {
            int row = rbase + 8 * h;
            if (row >= M) continue;
            int gidx = 0; bool valid = true;
            if (mode == 3) {
                win_map(row, gidx, valid);
                if (!valid) continue;
            }
            #pragma unroll
            for (int ni = 0; ni < 4; ni++) {
                int col = bn + wn * 32 + ni * 8 + tr * 2;
                float v0 = acc[mi][ni][2 * h]     + bias[col];
                float v1 = acc[mi][ni][2 * h + 1] + bias[col + 1];
                if (mode == 1) {
                    v0 = 0.5f * v0 * (1.f + erff(v0 * 0.70710678118654752f));
                    v1 = 0.5f * v1 * (1.f + erff(v1 * 0.70710678118654752f));
                    Cc[(size_t)row * N + col]     = v0;
                    Cc[(size_t)row * N + col + 1] = v1;
                } else if (mode == 2) {
                    Cc[(size_t)row * N + col]     = v0 + res[(size_t)row * N + col];
                    Cc[(size_t)row * N + col + 1] = v1 + res[(size_t)row * N + col + 1];
                } else if (mode == 3) {
                    Cc[(size_t)gidx * N + col]     = v0 + xin[(size_t)gidx * N + col];
                    Cc[(size_t)gidx * N + col + 1] = v1 + xin[(size_t)gidx * N + col + 1];
                } else {
                    Cc[(size_t)row * N + col]     = v0;
                    Cc[(size_t)row * N + col + 1] = v1;
                }
            }
        }
    }
}

// ---------------- fused window attention (conflict-free, vectorized) --------
#define KVS 68
#define ATTN_SMEM_FLOATS (HW*KVS*2 + 27*KVS*2 + 8*KVS + 8*28 + 8*200)

__global__ __launch_bounds__(256) void attn_kernel(
    const float* __restrict__ rel_h, const float* __restrict__ rel_w)
{
    extern __shared__ float sm[];
    float* ks = sm;                   // [196][68]
    float* vs = ks + HW * KVS;        // [196][68]
    float* rh = vs + HW * KVS;        // [27][68]
    float* rw = rh + 27 * KVS;        // [27][68]
    float* qs = rw + 27 * KVS;        // [8][68]
    float* bs = qs + 8 * KVS;         // [8][28]
    float* ps = bs + 8 * 28;          // [8][200]

    int w0   = blockIdx.x;
    int head = blockIdx.y;
    int tid  = threadIdx.x;
    int warp = tid >> 5, lane = tid & 31;

    const float* qkv_base = g_qkv + (size_t)w0 * HW * (3 * CDIM) + head * HD;
    for (int idx = tid; idx < HW * HD; idx += 256) {
        int kt = idx >> 6, d = idx & 63;
        const float* src = qkv_base + (size_t)kt * (3 * CDIM);
        ks[kt * KVS + d] = src[CDIM + d];
        vs[kt * KVS + d] = src[2 * CDIM + d];
    }
    for (int idx = tid; idx < 27 * HD; idx += 256) {
        int r = idx >> 6, d = idx & 63;
        rh[r * KVS + d] = rel_h[idx];
        rw[r * KVS + d] = rel_w[idx];
    }
    __syncthreads();

    int d0 = lane * 2;   // PV: lane owns dims d0, d0+1

    for (int r = warp; r < HW; r += 8) {
        size_t row = (size_t)w0 * HW + r;
        const float* qp = g_qkv + row * (3 * CDIM) + head * HD;
        qs[warp * KVS + lane]      = qp[lane];
        qs[warp * KVS + lane + 32] = qp[lane + 32];
        __syncwarp();

        int hq = r / WIN, wq = r % WIN;
        // decomposed rel-pos bias (tables padded -> conflict-free)
        if (lane < 28) {
            const float* tab; int o;
            if (lane < 14) { tab = rh; o = (hq - lane + (WIN - 1)) * KVS; }
            else           { tab = rw; o = (wq - (lane - 14) + (WIN - 1)) * KVS; }
            float sacc = 0.f;
            #pragma unroll
            for (int d = 0; d < HD; d += 4) {
                float4 q4 = *(const float4*)&qs[warp * KVS + d];
                float4 t4 = *(const float4*)&tab[o + d];
                sacc += q4.x * t4.x + q4.y * t4.y + q4.z * t4.z + q4.w * t4.w;
            }
            bs[warp * 28 + lane] = sacc;
        }
        __syncwarp();

        // scores: 7 keys per lane, d-outer float4
        float sc[7] = {0.f, 0.f, 0.f, 0.f, 0.f, 0.f, 0.f};
        int keyc[7];
        #pragma unroll
        for (int s = 0; s < 7; s++) {
            int key = lane + 32 * s;
            keyc[s] = key < HW ? key : HW - 1;
        }
        #pragma unroll 4
        for (int d = 0; d < HD; d += 4) {
            float4 q4 = *(const float4*)&qs[warp * KVS + d];
            #pragma unroll
            for (int s = 0; s < 7; s++) {
                float4 k4 = *(const float4*)&ks[keyc[s] * KVS + d];
                sc[s] += q4.x * k4.x + q4.y * k4.y + q4.z * k4.z + q4.w * k4.w;
            }
        }
        float mx = -1e30f;
        #pragma unroll
        for (int s = 0; s < 7; s++) {
            int key = lane + 32 * s;
            if (key < HW) {
                sc[s] = sc[s] * 0.125f
                      + bs[warp * 28 + key / WIN]
                      + bs[warp * 28 + 14 + key % WIN];
                mx = fmaxf(mx, sc[s]);
            } else sc[s] = -1e30f;
        }
        #pragma unroll
        for (int off = 16; off; off >>= 1)
            mx = fmaxf(mx, __shfl_xor_sync(~0u, mx, off));
        float sum = 0.f;
        #pragma unroll
        for (int s = 0; s < 7; s++) {
            int key = lane + 32 * s;
            if (key < HW) { float e = __expf(sc[s] - mx); sc[s] = e; sum += e; }
            else sc[s] = 0.f;
        }
        #pragma unroll
        for (int off = 16; off; off >>= 1)
            sum += __shfl_xor_sync(~0u, sum, off);
        float inv = 1.f / sum;
        #pragma unroll
        for (int s = 0; s < 7; s++) {
            int key = lane + 32 * s;
            if (key < HW) ps[warp * 200 + key] = sc[s] * inv;
        }
        __syncwarp();

        // out = P @ V : lane owns dims (d0, d0+1); float2 LDS, float4 prob bcast
        float o0 = 0.f, o1 = 0.f;
        #pragma unroll 4
        for (int k2 = 0; k2 < HW; k2 += 4) {
            float4 p4 = *(const float4*)&ps[warp * 200 + k2];
            float2 v0 = *(const float2*)&vs[(k2 + 0) * KVS + d0];
            float2 v1 = *(const float2*)&vs[(k2 + 1) * KVS + d0];
            float2 v2 = *(const float2*)&vs[(k2 + 2) * KVS + d0];
            float2 v3 = *(const float2*)&vs[(k2 + 3) * KVS + d0];
            o0 = fmaf(p4.x, v0.x, o0); o1 = fmaf(p4.x, v0.y, o1);
            o0 = fmaf(p4.y, v1.x, o0); o1 = fmaf(p4.y, v1.y, o1);
            o0 = fmaf(p4.z, v2.x, o0); o1 = fmaf(p4.z, v2.y, o1);
            o0 = fmaf(p4.w, v3.x, o0); o1 = fmaf(p4.w, v3.y, o1);
        }
        float* op = g_attn + row * CDIM + head * HD;
        *(float2*)&op[d0] = make_float2(o0, o1);
        __syncwarp();
    }
}

// ---------------- launcher ----------------
extern "C" void kernel_launch(void* const* d_in, const int* in_sizes, int n_in,
                              void* d_out, int out_size)
{
    const float* x      = (const float*)d_in[0];
    const float* g1     = (const float*)d_in[1];
    const float* b1     = (const float*)d_in[2];
    const float* w_qkv  = (const float*)d_in[3];
    const float* b_qkv  = (const float*)d_in[4];
    const float* w_proj = (const float*)d_in[5];
    const float* b_proj = (const float*)d_in[6];
    const float* rel_h  = (const float*)d_in[7];
    const float* rel_w  = (const float*)d_in[8];
    const float* g2     = (const float*)d_in[9];
    const float* b2     = (const float*)d_in[10];
    const float* w1     = (const float*)d_in[11];
    const float* b1m    = (const float*)d_in[12];
    const float* w2     = (const float*)d_in[13];
    const float* b2m    = (const float*)d_in[14];
    float* out = (float*)d_out;

    float *p_xw, *p_qkv, *p_attn, *p_x2, *p_xn2, *p_hid;
    cudaGetSymbolAddress((void**)&p_xw,   g_xw);
    cudaGetSymbolAddress((void**)&p_qkv,  g_qkv);
    cudaGetSymbolAddress((void**)&p_attn, g_attn);
    cudaGetSymbolAddress((void**)&p_x2,   g_x2);
    cudaGetSymbolAddress((void**)&p_xn2,  g_xn2);
    cudaGetSymbolAddress((void**)&p_hid,  g_hid);

    static int attr_set = 0;
    if (!attr_set) {
        cudaFuncSetAttribute(attn_kernel,
            cudaFuncAttributeMaxDynamicSharedMemorySize,
            ATTN_SMEM_FLOATS * sizeof(float));
        attr_set = 1;
    }

    // 1) LN1 + window partition -> g_xw [9800, 768]
    ln_win_kernel<<<TOKW, 256>>>(x, g1, b1);

    // 2) QKV GEMM: [9800,768] @ [768,2304]
    {
        dim3 grid((3 * CDIM) / 128, (TOKW + 127) / 128);
        tgemm_kernel<<<grid, 256>>>(p_xw, w_qkv, b_qkv, nullptr, nullptr,
                                    p_qkv, TOKW, 3 * CDIM, CDIM, 0);
    }

    // 3) fused attention per (window, head)
    attn_kernel<<<dim3(NW, NHEAD), 256, ATTN_SMEM_FLOATS * sizeof(float)>>>(rel_h, rel_w);

    // 4) proj GEMM + window unpartition + residual -> g_x2 [8192, 768]
    {
        dim3 grid(CDIM / 128, (TOKW + 127) / 128);
        tgemm_kernel<<<grid, 256>>>(p_attn, w_proj, b_proj, nullptr, x,
                                    p_x2, TOKW, CDIM, CDIM, 3);
    }

    // 5) LN2 -> g_xn2
    ln2_kernel<<<TOKG, 256>>>(g2, b2);

    // 6) FC1 + GELU: [8192,768] @ [768,3072]
    {
        dim3 grid(MLPD / 128, TOKG / 128);
        tgemm_kernel<<<grid, 256>>>(p_xn2, w1, b1m, nullptr, nullptr,
                                    p_hid, TOKG, MLPD, CDIM, 1);
    }

    // 7) FC2 + residual: [8192,3072] @ [3072,768] -> out
    {
        dim3 grid(CDIM / 128, TOKG / 128);
        tgemm_kernel<<<grid, 256>>>(p_hid, w2, b2m, p_x2, nullptr,
                                    out, TOKG, CDIM, MLPD, 2);
    }
}